// round 13
// baseline (speedup 1.0000x reference)
#include <cuda_runtime.h>
#include <cuda_bf16.h>
#include <math_constants.h>

// Problem constants
#define NX 1024
#define NY 1024
#define DIM 128
#define DIM2 (DIM / 2)      // 64 packed f32x2 lanes per row
#define NCM1 4              // n_classes - 1

#define BI 32
#define BJ 32
#define NTILE 32            // 32x32 grid of 32x32 tiles
#define NCTA 512
#define TILES_PER_CTA 2     // 1024 tiles / 512 CTAs

typedef unsigned long long u64;

// ---------------- scratch (no allocations allowed) ----------------
__device__ float g_S[NX * NY];               // s matrix, 4 MB (L2-resident)
__device__ float g_prow[NTILE * NX * 2];     // (max,sum) per (tileJ, row)
__device__ float g_pcol[NTILE * NY * 2];     // (max,sum) per (tileI, col)
__device__ float g_rowmax[NX];
__device__ float g_rowsuminv[NX];
__device__ float g_colmax[NY];
__device__ float g_colsuminv[NY];
__device__ float g_part[NX * 2];             // per-row partial (sum_a, sum_a*s)
__device__ int   g_rowctr[NTILE];
__device__ int   g_colctr[NTILE];
__device__ int   g_bar;                      // grid barrier arrivals
__device__ int   g_combctr;                  // phase-2 arrivals

// ---------------- packed f32x2 helpers ----------------
__device__ __forceinline__ u64 add2(u64 a, u64 b) {
    u64 r;
    asm("add.rn.f32x2 %0, %1, %2;" : "=l"(r) : "l"(a), "l"(b));
    return r;
}
// |x + yneg| where yneg already holds -y ; abs via sign-bit clear (ALU pipe)
__device__ __forceinline__ u64 absdiff2(u64 x, u64 yneg) {
    return add2(x, yneg) & 0x7FFFFFFF7FFFFFFFULL;
}

// ---------------- single persistent kernel, 512 co-resident CTAs ----------------
// Phase 1: 2 tiles/CTA, full-depth staged (2 syncs/tile), tid0-only fences.
// Grid barrier (all 512 CTAs co-resident: smem 36.2KB*4=145KB<=228KB, regs 64*256*4=64K).
// Phase 2: 2 rows/CTA combine; last CTA reduces to logits.
__global__ __launch_bounds__(256, 4) void k_fused(const float* __restrict__ zx,
                                                  const float* __restrict__ zy,
                                                  const float* __restrict__ theta,
                                                  const float* __restrict__ beta,
                                                  float* __restrict__ out) {
    __shared__ u64 Xs[DIM2][BI + 1];      // 16.9 KB
    __shared__ u64 Ys[DIM2][BJ + 1];      // 16.9 KB
    __shared__ float cred[16][BJ + 1];    // 2.1 KB
    __shared__ float cmaxs[BJ];
    __shared__ float ra[8], rb[8];
    __shared__ int lastRow, lastCol, lastc;

    const int tid = threadIdx.x;
    const int tx = tid & 15;
    const int ty = tid >> 4;
    const int cta = blockIdx.x;
    const unsigned FULL = 0xffffffffu;

    const u64* zx2 = (const u64*)zx;
    const u64* zy2 = (const u64*)zy;

    // ================= PHASE 1 =================
    #pragma unroll
    for (int tt = 0; tt < TILES_PER_CTA; ++tt) {
        const int tile = cta + tt * NCTA;       // 0..1023
        const int by = tile >> 5;               // tileI
        const int bx = tile & 31;               // tileJ
        const int i0 = by * BI;
        const int j0 = bx * BJ;

        // stage full depth: 32 rows x 64 d-pairs per operand, 8 u64/thread
        #pragma unroll
        for (int s = 0; s < 8; ++s) {
            int t = tid + s * 256;
            int d = t & (DIM2 - 1);
            int r = t >> 6;
            Xs[d][r] = zx2[(u64)(i0 + r) * DIM2 + d];
            Ys[d][r] = zy2[(u64)(j0 + r) * DIM2 + d] ^ 0x8000000080000000ULL; // pre-negate
        }
        __syncthreads();

        u64 acc00 = 0, acc01 = 0, acc10 = 0, acc11 = 0;
        #pragma unroll 16
        for (int d = 0; d < DIM2; ++d) {
            u64 x0 = Xs[d][ty];
            u64 x1 = Xs[d][ty + 16];
            u64 y0 = Ys[d][tx];
            u64 y1 = Ys[d][tx + 16];
            acc00 = add2(acc00, absdiff2(x0, y0));
            acc01 = add2(acc01, absdiff2(x0, y1));
            acc10 = add2(acc10, absdiff2(x1, y0));
            acc11 = add2(acc11, absdiff2(x1, y1));
        }

        float2 a00 = *(float2*)&acc00;
        float2 a01 = *(float2*)&acc01;
        float2 a10 = *(float2*)&acc10;
        float2 a11 = *(float2*)&acc11;

        const float s00 = -(a00.x + a00.y);
        const float s01 = -(a01.x + a01.y);
        const float s10 = -(a10.x + a10.y);
        const float s11 = -(a11.x + a11.y);

        g_S[(i0 + ty     ) * NY + j0 + tx     ] = s00;
        g_S[(i0 + ty     ) * NY + j0 + tx + 16] = s01;
        g_S[(i0 + ty + 16) * NY + j0 + tx     ] = s10;
        g_S[(i0 + ty + 16) * NY + j0 + tx + 16] = s11;

        // ---- row partials: 16 threads sharing ty form one half-warp ----
        float m0 = fmaxf(s00, s01);
        float m1 = fmaxf(s10, s11);
        #pragma unroll
        for (int o = 8; o > 0; o >>= 1) {
            m0 = fmaxf(m0, __shfl_xor_sync(FULL, m0, o));
            m1 = fmaxf(m1, __shfl_xor_sync(FULL, m1, o));
        }
        float e0 = __expf(s00 - m0) + __expf(s01 - m0);
        float e1 = __expf(s10 - m1) + __expf(s11 - m1);
        #pragma unroll
        for (int o = 8; o > 0; o >>= 1) {
            e0 += __shfl_xor_sync(FULL, e0, o);
            e1 += __shfl_xor_sync(FULL, e1, o);
        }
        if (tx == 0) {
            g_prow[(bx * NX + i0 + ty     ) * 2 + 0] = m0;
            g_prow[(bx * NX + i0 + ty     ) * 2 + 1] = e0;
            g_prow[(bx * NX + i0 + ty + 16) * 2 + 0] = m1;
            g_prow[(bx * NX + i0 + ty + 16) * 2 + 1] = e1;
        }

        // ---- col partials via smem ----
        cred[ty][tx     ] = fmaxf(s00, s10);
        cred[ty][tx + 16] = fmaxf(s01, s11);
        __syncthreads();
        if (tid < 32) {
            float m = cred[0][tid];
            #pragma unroll
            for (int r = 1; r < 16; ++r) m = fmaxf(m, cred[r][tid]);
            cmaxs[tid] = m;
        }
        __syncthreads();
        {
            const float cm0 = cmaxs[tx];
            const float cm1 = cmaxs[tx + 16];
            cred[ty][tx     ] = __expf(s00 - cm0) + __expf(s10 - cm0);
            cred[ty][tx + 16] = __expf(s01 - cm1) + __expf(s11 - cm1);
        }
        __syncthreads();
        if (tid < 32) {
            float s = 0.f;
            #pragma unroll
            for (int r = 0; r < 16; ++r) s += cred[r][tid];
            g_pcol[(by * NY + j0 + tid) * 2 + 0] = cmaxs[tid];
            g_pcol[(by * NY + j0 + tid) * 2 + 1] = s;
        }

        // ---- strip arrival: syncthreads establishes intra-CTA HB; tid0 fence+atomic
        //      publishes (release); only tid0 pays the MEMBAR.GPU.
        __syncthreads();
        if (tid == 0) {
            __threadfence();
            lastRow = (atomicAdd(&g_rowctr[by], 1) == NTILE - 1);
            lastCol = (atomicAdd(&g_colctr[bx], 1) == NTILE - 1);
        }
        __syncthreads();

        if (lastRow) {
            if (tid < 32) {
                const int i = i0 + tid;
                float m = -CUDART_INF_F;
                #pragma unroll
                for (int p = 0; p < NTILE; ++p)
                    m = fmaxf(m, g_prow[(p * NX + i) * 2 + 0]);
                float s = 0.f;
                #pragma unroll
                for (int p = 0; p < NTILE; ++p)
                    s += g_prow[(p * NX + i) * 2 + 1] * __expf(g_prow[(p * NX + i) * 2 + 0] - m);
                g_rowmax[i] = m;
                g_rowsuminv[i] = 1.0f / s;
            }
            if (tid == 0) g_rowctr[by] = 0;   // reset for graph replay
        }
        if (lastCol) {
            if (tid >= 224) {
                const int j = j0 + (tid - 224);
                float m = -CUDART_INF_F;
                #pragma unroll
                for (int p = 0; p < NTILE; ++p)
                    m = fmaxf(m, g_pcol[(p * NY + j) * 2 + 0]);
                float s = 0.f;
                #pragma unroll
                for (int p = 0; p < NTILE; ++p)
                    s += g_pcol[(p * NY + j) * 2 + 1] * __expf(g_pcol[(p * NY + j) * 2 + 0] - m);
                g_colmax[j] = m;
                g_colsuminv[j] = 1.0f / s;
            }
            if (tid == 224) g_colctr[bx] = 0; // reset for graph replay
        }
    }

    // ================= GRID BARRIER =================
    __syncthreads();
    if (tid == 0) {
        __threadfence();                     // release this CTA's phase-1 writes
        atomicAdd(&g_bar, 1);
        volatile int* vb = &g_bar;
        while (*vb < NCTA) { }
        __threadfence();                     // acquire other CTAs' publishes
    }
    __syncthreads();

    // ================= PHASE 2 =================
    // 2 rows per CTA; group g (128 threads) handles row cta*2+g, 2 float4/thread.
    {
        const int lane = tid & 127;
        const int grp  = tid >> 7;
        const int row  = cta * 2 + grp;
        const float rm = g_rowmax[row];
        const float ri = g_rowsuminv[row];
        const float4* S4  = (const float4*)(g_S + row * NY);
        const float4* cm4 = (const float4*)g_colmax;
        const float4* ci4 = (const float4*)g_colsuminv;

        float pa = 0.f, pas = 0.f;
        #pragma unroll
        for (int k = 0; k < 2; ++k) {
            const int idx = lane + 128 * k;
            const float4 s  = S4[idx];
            const float4 cm = cm4[idx];
            const float4 ci = ci4[idx];
            float ea, eb, a;
            ea = __expf(s.x - rm) * ri; eb = __expf(s.x - cm.x) * ci.x;
            a = ea + eb - ea * eb; pa += a; pas += a * s.x;
            ea = __expf(s.y - rm) * ri; eb = __expf(s.y - cm.y) * ci.y;
            a = ea + eb - ea * eb; pa += a; pas += a * s.y;
            ea = __expf(s.z - rm) * ri; eb = __expf(s.z - cm.z) * ci.z;
            a = ea + eb - ea * eb; pa += a; pas += a * s.z;
            ea = __expf(s.w - rm) * ri; eb = __expf(s.w - cm.w) * ci.w;
            a = ea + eb - ea * eb; pa += a; pas += a * s.w;
        }

        #pragma unroll
        for (int o = 16; o > 0; o >>= 1) {
            pa  += __shfl_xor_sync(FULL, pa,  o);
            pas += __shfl_xor_sync(FULL, pas, o);
        }
        if ((tid & 31) == 0) { ra[tid >> 5] = pa; rb[tid >> 5] = pas; }
        __syncthreads();
        if ((tid & 127) == 0) {
            const int w = grp * 4;
            g_part[row * 2 + 0] = (ra[w] + ra[w + 1]) + (ra[w + 2] + ra[w + 3]);
            g_part[row * 2 + 1] = (rb[w] + rb[w + 1]) + (rb[w + 2] + rb[w + 3]);
        }
        __syncthreads();
        if (tid == 0) {
            __threadfence();
            lastc = (atomicAdd(&g_combctr, 1) == NCTA - 1);
        }
        __syncthreads();

        if (lastc) {
            float a = 0.f, b = 0.f;
            #pragma unroll
            for (int r = tid; r < NX; r += 256) {
                a += g_part[2 * r + 0];
                b += g_part[2 * r + 1];
            }
            #pragma unroll
            for (int o = 16; o > 0; o >>= 1) {
                a += __shfl_xor_sync(FULL, a, o);
                b += __shfl_xor_sync(FULL, b, o);
            }
            if ((tid & 31) == 0) { ra[tid >> 5] = a; rb[tid >> 5] = b; }
            __syncthreads();
            if (tid < NCM1) {
                float fa = 0.f, fb = 0.f;
                #pragma unroll
                for (int w = 0; w < 8; ++w) { fa += ra[w]; fb += rb[w]; }
                float c = fb / fa;
                out[tid] = c * theta[tid] + beta[tid];
            }
            if (tid == 0) { g_combctr = 0; g_bar = 0; }   // reset for graph replay
        }
    }
}

// ---------------- launch (ONE kernel; graph-capture safe) ----------------
extern "C" void kernel_launch(void* const* d_in, const int* in_sizes, int n_in,
                              void* d_out, int out_size) {
    const float* zx    = (const float*)d_in[0];   // (1024,128)
    const float* zy    = (const float*)d_in[1];   // (1024,128)
    const float* theta = (const float*)d_in[2];   // (1,4)
    const float* beta  = (const float*)d_in[3];   // (4,)
    float* out = (float*)d_out;

    k_fused<<<NCTA, 256>>>(zx, zy, theta, beta, out);
}

// round 15
// speedup vs baseline: 1.1609x; 1.1609x over previous
#include <cuda_runtime.h>
#include <cuda_bf16.h>
#include <math_constants.h>

// Problem constants
#define NX 1024
#define NY 1024
#define DIM 128
#define DIM2 (DIM / 2)      // 64 packed f32x2 lanes per row
#define NCM1 4              // n_classes - 1

// K1 tiling: 32(i) x 64(j) tile, 256 threads (16x16), 2x4 outputs/thread
#define BI 32
#define BJ 64
#define DC 32               // d-pairs per staged chunk (2 chunks)
#define NTI 32              // i-strips (1024/32)
#define NTJ 16              // j-strips (1024/64)

typedef unsigned long long u64;

// ---------------- scratch (no allocations allowed) ----------------
__device__ float g_S[NX * NY];               // s matrix, 4 MB (L2-resident)
__device__ float g_prow[NTJ * NX * 2];       // (max,sum) per (j-strip, row)
__device__ float g_pcol[NTI * NY * 2];       // (max,sum) per (i-strip, col)
__device__ float g_rowmax[NX];
__device__ float g_rowsuminv[NX];
__device__ float g_colmax[NY];
__device__ float g_colsuminv[NY];
__device__ float g_part[NX * 2];             // per-row partial (sum_a, sum_a*s)
__device__ int   g_rowctr[NTI];              // arrivals per i-strip (count to NTJ)
__device__ int   g_colctr[NTJ];              // arrivals per j-strip (count to NTI)
__device__ int   g_combctr;

// ---------------- packed f32x2 helpers ----------------
__device__ __forceinline__ u64 add2(u64 a, u64 b) {
    u64 r;
    asm("add.rn.f32x2 %0, %1, %2;" : "=l"(r) : "l"(a), "l"(b));
    return r;
}
// |x + yneg| where yneg already holds -y ; abs via sign-bit clear (ALU pipe)
__device__ __forceinline__ u64 absdiff2(u64 x, u64 yneg) {
    return add2(x, yneg) & 0x7FFFFFFF7FFFFFFFULL;
}

// ---------------- K1: 32x64 S tile + fused partials + distributed strip merge ------
__global__ __launch_bounds__(256) void k_s(const float* __restrict__ zx,
                                           const float* __restrict__ zy) {
    __shared__ u64 Xs[DC][BI + 1];        // 8.25 KB
    __shared__ u64 Ys[DC][BJ + 1];        // 16.25 KB
    __shared__ float cred[16][BJ + 1];    // 4.06 KB
    __shared__ float cmaxs[BJ];
    __shared__ int lastRow, lastCol;

    const int tid = threadIdx.x;
    const int tx = tid & 15;
    const int ty = tid >> 4;
    const int bx = blockIdx.x;            // j-strip 0..15
    const int by = blockIdx.y;            // i-strip 0..31
    const int i0 = by * BI;
    const int j0 = bx * BJ;
    const unsigned FULL = 0xffffffffu;

    const u64* zx2 = (const u64*)zx;
    const u64* zy2 = (const u64*)zy;

    u64 acc[2][4];
    #pragma unroll
    for (int a = 0; a < 2; ++a)
        #pragma unroll
        for (int b = 0; b < 4; ++b) acc[a][b] = 0;

    #pragma unroll
    for (int dc = 0; dc < DIM2; dc += DC) {
        // stage: Y 64 rows x 32 d-pairs (8 iters), X 32 rows x 32 d-pairs (4 iters)
        #pragma unroll
        for (int s = 0; s < 8; ++s) {
            int t = tid + s * 256;
            int d = t & (DC - 1);
            int r = t >> 5;               // 0..63
            Ys[d][r] = zy2[(u64)(j0 + r) * DIM2 + dc + d] ^ 0x8000000080000000ULL;
            if (s < 4)
                Xs[d][r] = zx2[(u64)(i0 + r) * DIM2 + dc + d];
        }
        __syncthreads();

        #pragma unroll 8
        for (int d = 0; d < DC; ++d) {
            u64 x0 = Xs[d][ty];
            u64 x1 = Xs[d][ty + 16];
            u64 y0 = Ys[d][tx];
            u64 y1 = Ys[d][tx + 16];
            u64 y2 = Ys[d][tx + 32];
            u64 y3 = Ys[d][tx + 48];
            acc[0][0] = add2(acc[0][0], absdiff2(x0, y0));
            acc[0][1] = add2(acc[0][1], absdiff2(x0, y1));
            acc[0][2] = add2(acc[0][2], absdiff2(x0, y2));
            acc[0][3] = add2(acc[0][3], absdiff2(x0, y3));
            acc[1][0] = add2(acc[1][0], absdiff2(x1, y0));
            acc[1][1] = add2(acc[1][1], absdiff2(x1, y1));
            acc[1][2] = add2(acc[1][2], absdiff2(x1, y2));
            acc[1][3] = add2(acc[1][3], absdiff2(x1, y3));
        }
        __syncthreads();
    }

    // finalize s values and store S
    float sv[2][4];
    #pragma unroll
    for (int a = 0; a < 2; ++a) {
        #pragma unroll
        for (int b = 0; b < 4; ++b) {
            float2 p = *(float2*)&acc[a][b];
            sv[a][b] = -(p.x + p.y);
            g_S[(i0 + ty + 16 * a) * NY + j0 + tx + 16 * b] = sv[a][b];
        }
    }

    // ---- row partials: 16 lanes sharing ty form one half-warp ----
    #pragma unroll
    for (int a = 0; a < 2; ++a) {
        float m = fmaxf(fmaxf(sv[a][0], sv[a][1]), fmaxf(sv[a][2], sv[a][3]));
        #pragma unroll
        for (int o = 8; o > 0; o >>= 1)
            m = fmaxf(m, __shfl_xor_sync(FULL, m, o));
        float e = __expf(sv[a][0] - m) + __expf(sv[a][1] - m)
                + __expf(sv[a][2] - m) + __expf(sv[a][3] - m);
        #pragma unroll
        for (int o = 8; o > 0; o >>= 1)
            e += __shfl_xor_sync(FULL, e, o);
        if (tx == 0) {
            const int i = i0 + ty + 16 * a;
            g_prow[(bx * NX + i) * 2 + 0] = m;
            g_prow[(bx * NX + i) * 2 + 1] = e;
        }
    }

    // ---- col partials via smem (64 cols) ----
    #pragma unroll
    for (int b = 0; b < 4; ++b)
        cred[ty][tx + 16 * b] = fmaxf(sv[0][b], sv[1][b]);
    __syncthreads();
    if (tid < 64) {
        float m = cred[0][tid];
        #pragma unroll
        for (int r = 1; r < 16; ++r) m = fmaxf(m, cred[r][tid]);
        cmaxs[tid] = m;
    }
    __syncthreads();
    #pragma unroll
    for (int b = 0; b < 4; ++b) {
        const float cm = cmaxs[tx + 16 * b];
        cred[ty][tx + 16 * b] = __expf(sv[0][b] - cm) + __expf(sv[1][b] - cm);
    }
    __syncthreads();
    if (tid < 64) {
        float s = 0.f;
        #pragma unroll
        for (int r = 0; r < 16; ++r) s += cred[r][tid];
        g_pcol[(by * NY + j0 + tid) * 2 + 0] = cmaxs[tid];
        g_pcol[(by * NY + j0 + tid) * 2 + 1] = s;
    }

    // ---- strip arrival: tid0-only fence + counters ----
    __syncthreads();
    if (tid == 0) {
        __threadfence();
        lastRow = (atomicAdd(&g_rowctr[by], 1) == NTJ - 1);
        lastCol = (atomicAdd(&g_colctr[bx], 1) == NTI - 1);
    }
    __syncthreads();

    if (lastRow) {
        // 32 rows of this i-strip, 16 j-partials each (fixed order)
        if (tid < 32) {
            const int i = i0 + tid;
            float m = -CUDART_INF_F;
            #pragma unroll
            for (int p = 0; p < NTJ; ++p)
                m = fmaxf(m, g_prow[(p * NX + i) * 2 + 0]);
            float s = 0.f;
            #pragma unroll
            for (int p = 0; p < NTJ; ++p)
                s += g_prow[(p * NX + i) * 2 + 1] * __expf(g_prow[(p * NX + i) * 2 + 0] - m);
            g_rowmax[i] = m;
            g_rowsuminv[i] = 1.0f / s;
        }
        if (tid == 0) g_rowctr[by] = 0;   // reset for graph replay
    }
    if (lastCol) {
        // 64 cols of this j-strip, 32 i-partials each
        if (tid >= 192) {
            const int j = j0 + (tid - 192);
            float m = -CUDART_INF_F;
            #pragma unroll
            for (int p = 0; p < NTI; ++p)
                m = fmaxf(m, g_pcol[(p * NY + j) * 2 + 0]);
            float s = 0.f;
            #pragma unroll
            for (int p = 0; p < NTI; ++p)
                s += g_pcol[(p * NY + j) * 2 + 1] * __expf(g_pcol[(p * NY + j) * 2 + 0] - m);
            g_colmax[j] = m;
            g_colsuminv[j] = 1.0f / s;
        }
        if (tid == 192) g_colctr[bx] = 0; // reset for graph replay
    }
}

// ---------------- K2: combine + per-row partials + last-block logits ----------------
// 1024 blocks x 128 threads; 8 elems/thread via two float4 loads (proven 6.8us shape).
__global__ __launch_bounds__(128) void k_comb(const float* __restrict__ theta,
                                              const float* __restrict__ beta,
                                              float* __restrict__ out) {
    const int i = blockIdx.x;
    const int t = threadIdx.x;
    const float rm = g_rowmax[i];
    const float ri = g_rowsuminv[i];

    const float4* S4  = (const float4*)(g_S + i * NY);
    const float4* cm4 = (const float4*)g_colmax;
    const float4* ci4 = (const float4*)g_colsuminv;

    float pa = 0.f, pas = 0.f;
    #pragma unroll
    for (int kk = 0; kk < 2; ++kk) {
        const int idx = t + kk * 128;
        const float4 s  = S4[idx];
        const float4 cm = cm4[idx];
        const float4 ci = ci4[idx];

        float ea, eb, a;
        ea = __expf(s.x - rm) * ri; eb = __expf(s.x - cm.x) * ci.x;
        a = ea + eb - ea * eb; pa += a; pas += a * s.x;
        ea = __expf(s.y - rm) * ri; eb = __expf(s.y - cm.y) * ci.y;
        a = ea + eb - ea * eb; pa += a; pas += a * s.y;
        ea = __expf(s.z - rm) * ri; eb = __expf(s.z - cm.z) * ci.z;
        a = ea + eb - ea * eb; pa += a; pas += a * s.z;
        ea = __expf(s.w - rm) * ri; eb = __expf(s.w - cm.w) * ci.w;
        a = ea + eb - ea * eb; pa += a; pas += a * s.w;
    }

    const unsigned FULL = 0xffffffffu;
    #pragma unroll
    for (int o = 16; o > 0; o >>= 1) {
        pa  += __shfl_xor_sync(FULL, pa,  o);
        pas += __shfl_xor_sync(FULL, pas, o);
    }

    __shared__ float sa[4];
    __shared__ float sb[4];
    __shared__ int last;
    const int wid = t >> 5;
    if ((t & 31) == 0) { sa[wid] = pa; sb[wid] = pas; }
    __syncthreads();
    if (t == 0) {
        g_part[i * 2 + 0] = (sa[0] + sa[1]) + (sa[2] + sa[3]);
        g_part[i * 2 + 1] = (sb[0] + sb[1]) + (sb[2] + sb[3]);
        __threadfence();
        last = (atomicAdd(&g_combctr, 1) == NX - 1);
    }
    __syncthreads();

    if (last) {
        float a = 0.f, b = 0.f;
        #pragma unroll
        for (int r = t; r < NX; r += 128) {
            a += g_part[2 * r + 0];
            b += g_part[2 * r + 1];
        }
        #pragma unroll
        for (int o = 16; o > 0; o >>= 1) {
            a += __shfl_xor_sync(FULL, a, o);
            b += __shfl_xor_sync(FULL, b, o);
        }
        if ((t & 31) == 0) { sa[wid] = a; sb[wid] = b; }
        __syncthreads();
        if (t < NCM1) {
            float fa = (sa[0] + sa[1]) + (sa[2] + sa[3]);
            float fb = (sb[0] + sb[1]) + (sb[2] + sb[3]);
            float c = fb / fa;
            out[t] = c * theta[t] + beta[t];
        }
        if (t == 0) g_combctr = 0;    // reset for graph replay
    }
}

// ---------------- launch (2 kernels; graph-capture safe) ----------------
extern "C" void kernel_launch(void* const* d_in, const int* in_sizes, int n_in,
                              void* d_out, int out_size) {
    const float* zx    = (const float*)d_in[0];   // (1024,128)
    const float* zy    = (const float*)d_in[1];   // (1024,128)
    const float* theta = (const float*)d_in[2];   // (1,4)
    const float* beta  = (const float*)d_in[3];   // (4,)
    float* out = (float*)d_out;

    k_s<<<dim3(NTJ, NTI), 256>>>(zx, zy);         // 512 blocks
    k_comb<<<NX, 128>>>(theta, beta, out);        // 1024 blocks
}